// round 4
// baseline (speedup 1.0000x reference)
#include <cuda_runtime.h>

#define Bb 8
#define Nn 1024
#define Cc 1024
#define Hh 16
#define Dd 64

// Scratch (device globals: allocation-free per harness rules)
__device__ float g_q[Bb * Hh * Nn * Dd];    // [B,H,N,D]
__device__ float g_k[Bb * Hh * Nn * Dd];
__device__ float g_v[Bb * Hh * Nn * Dd];
__device__ float g_ao[Bb * Nn * Cc];        // attention out, [B,N,C]

// ---------------------------------------------------------------------------
// TN SGEMM: C[m,n] = sum_k A[m,k] * W[n,k] + bias[n]
// Tile: BM=128, BN=64, BK=16. 256 threads, 8x4 outputs/thread.
// EPI=0: A = x (8192x1024), Ndim=3072, scatter into g_q/g_k/g_v.
// EPI=1: A = g_ao (8192x1024), Ndim=1024, write to out.
// ---------------------------------------------------------------------------
template <int EPI>
__global__ __launch_bounds__(256) void gemm_tn(const float* __restrict__ Ain,
                                               const float* __restrict__ W,
                                               const float* __restrict__ bias,
                                               float* __restrict__ out)
{
    const float* __restrict__ A = (EPI == 0) ? Ain : g_ao;

    __shared__ __align__(16) float As[16][128];   // [k][m]
    __shared__ __align__(16) float Bs[16][64];    // [k][n]

    const int tid = threadIdx.x;
    const int cx = tid & 15;          // output col group (4 cols)
    const int cy = tid >> 4;          // output row group (8 rows)
    const int bn = blockIdx.x * 64;
    const int bm = blockIdx.y * 128;

    float acc[8][4];
#pragma unroll
    for (int i = 0; i < 8; i++)
#pragma unroll
        for (int j = 0; j < 4; j++) acc[i][j] = 0.0f;

    for (int k0 = 0; k0 < 1024; k0 += 16) {
        // Load A tile (128x16) transposed into As[k][m]
#pragma unroll
        for (int u = 0; u < 2; u++) {
            int i = tid + u * 256;            // 0..511 float4s
            int row = i >> 2;                 // 0..127
            int c = i & 3;                    // float4 within 16-wide k chunk
            float4 f = *(const float4*)(A + (size_t)(bm + row) * 1024 + k0 + 4 * c);
            As[4 * c + 0][row] = f.x;
            As[4 * c + 1][row] = f.y;
            As[4 * c + 2][row] = f.z;
            As[4 * c + 3][row] = f.w;
        }
        // Load W tile (64x16) transposed into Bs[k][n]
        {
            int row = tid >> 2;               // 0..63
            int c = tid & 3;
            float4 f = *(const float4*)(W + (size_t)(bn + row) * 1024 + k0 + 4 * c);
            Bs[4 * c + 0][row] = f.x;
            Bs[4 * c + 1][row] = f.y;
            Bs[4 * c + 2][row] = f.z;
            Bs[4 * c + 3][row] = f.w;
        }
        __syncthreads();

#pragma unroll
        for (int k = 0; k < 16; k++) {
            float4 a0 = *(const float4*)&As[k][cy * 8];
            float4 a1 = *(const float4*)&As[k][cy * 8 + 4];
            float4 b  = *(const float4*)&Bs[k][cx * 4];
            float av[8] = {a0.x, a0.y, a0.z, a0.w, a1.x, a1.y, a1.z, a1.w};
            float bv[4] = {b.x, b.y, b.z, b.w};
#pragma unroll
            for (int ii = 0; ii < 8; ii++)
#pragma unroll
                for (int jj = 0; jj < 4; jj++)
                    acc[ii][jj] = fmaf(av[ii], bv[jj], acc[ii][jj]);
        }
        __syncthreads();
    }

    // Epilogue
#pragma unroll
    for (int ii = 0; ii < 8; ii++) {
#pragma unroll
        for (int jj = 0; jj < 4; jj++) {
            int m = bm + cy * 8 + ii;
            int n = bn + cx * 4 + jj;
            float v = acc[ii][jj] + bias[n];
            if (EPI == 0) {
                // n = s*1024 + h*64 + d ; m = b*1024 + nn
                int b = m >> 10, nn = m & 1023;
                int s = n >> 10;
                int h = (n >> 6) & 15;
                int d = n & 63;
                float* dst = (s == 0) ? g_q : (s == 1) ? g_k : g_v;
                dst[(((size_t)b * Hh + h) * Nn + nn) * Dd + d] = v;
            } else {
                out[(size_t)m * 1024 + n] = v;
            }
        }
    }
}

// ---------------------------------------------------------------------------
// Flash attention (fp32). One CTA = (64 Q rows) x (one b,h). 256 threads.
// 16x16 thread grid, 4x4 outputs per thread. Online softmax in registers.
// Smem: Qt[64d][68] (K-transposed, scale folded in), KPt[64][68] (K tile,
// reused as transposed-P tile), Vs[64][64]. Total 51200 B (dynamic).
// ---------------------------------------------------------------------------
__global__ __launch_bounds__(256) void attn_kernel()
{
    extern __shared__ __align__(16) float sm[];
    float* Qt  = sm;                  // Qt[d*68 + i]
    float* KPt = sm + 64 * 68;        // Kt[d*68 + j]  /  Pt[kk*68 + i]
    float* Vs  = sm + 2 * 64 * 68;    // Vs[kk*64 + d]

    const int tid = threadIdx.x;
    const int tx = tid & 15;          // col group
    const int ty = tid >> 4;          // row group
    const int bh = blockIdx.y;        // 0..127 = b*16 + h
    const int q0 = blockIdx.x * 64;

    const float* Qp = g_q + (size_t)bh * Nn * Dd;
    const float* Kp = g_k + (size_t)bh * Nn * Dd;
    const float* Vp = g_v + (size_t)bh * Nn * Dd;
    const float scale = 0.125f;       // 64^-0.5

    // Load Q tile transposed, folding in the softmax scale
#pragma unroll
    for (int u = 0; u < 4; u++) {
        int i = tid + u * 256;        // 0..1023 float4s
        int row = i >> 4, c = i & 15;
        float4 f = *(const float4*)(Qp + (size_t)(q0 + row) * 64 + 4 * c);
        Qt[(4 * c + 0) * 68 + row] = f.x * scale;
        Qt[(4 * c + 1) * 68 + row] = f.y * scale;
        Qt[(4 * c + 2) * 68 + row] = f.z * scale;
        Qt[(4 * c + 3) * 68 + row] = f.w * scale;
    }
    __syncthreads();

    float o[4][4];
    float mrow[4], lrow[4];
#pragma unroll
    for (int ii = 0; ii < 4; ii++) {
        mrow[ii] = -1e30f;
        lrow[ii] = 0.0f;
#pragma unroll
        for (int jj = 0; jj < 4; jj++) o[ii][jj] = 0.0f;
    }

    for (int t = 0; t < 16; t++) {
        const float* Kt0 = Kp + (size_t)t * 64 * 64;
        const float* Vt0 = Vp + (size_t)t * 64 * 64;
#pragma unroll
        for (int u = 0; u < 4; u++) {
            int i = tid + u * 256;
            int row = i >> 4, c = i & 15;
            float4 f = *(const float4*)(Kt0 + (size_t)row * 64 + 4 * c);
            KPt[(4 * c + 0) * 68 + row] = f.x;
            KPt[(4 * c + 1) * 68 + row] = f.y;
            KPt[(4 * c + 2) * 68 + row] = f.z;
            KPt[(4 * c + 3) * 68 + row] = f.w;
            float4 g = *(const float4*)(Vt0 + (size_t)row * 64 + 4 * c);
            *(float4*)&Vs[row * 64 + 4 * c] = g;
        }
        __syncthreads();

        // S = (scaled Q) K^T  (4x4 per thread)
        float s[4][4];
#pragma unroll
        for (int ii = 0; ii < 4; ii++)
#pragma unroll
            for (int jj = 0; jj < 4; jj++) s[ii][jj] = 0.0f;

#pragma unroll 8
        for (int d = 0; d < 64; d++) {
            float4 qv = *(const float4*)&Qt[d * 68 + 4 * ty];
            float4 kv = *(const float4*)&KPt[d * 68 + 4 * tx];
            float qa[4] = {qv.x, qv.y, qv.z, qv.w};
            float ka[4] = {kv.x, kv.y, kv.z, kv.w};
#pragma unroll
            for (int ii = 0; ii < 4; ii++)
#pragma unroll
                for (int jj = 0; jj < 4; jj++)
                    s[ii][jj] = fmaf(qa[ii], ka[jj], s[ii][jj]);
        }

        // Online softmax: reduce over the 16 tx lanes (xor butterflies 1..8)
#pragma unroll
        for (int ii = 0; ii < 4; ii++) {
            float mx = fmaxf(fmaxf(s[ii][0], s[ii][1]), fmaxf(s[ii][2], s[ii][3]));
#pragma unroll
            for (int msk = 1; msk < 16; msk <<= 1)
                mx = fmaxf(mx, __shfl_xor_sync(0xffffffffu, mx, msk));
            float mnew = fmaxf(mrow[ii], mx);
            float corr = __expf(mrow[ii] - mnew);
            float sum = 0.0f;
#pragma unroll
            for (int jj = 0; jj < 4; jj++) {
                s[ii][jj] = __expf(s[ii][jj] - mnew);
                sum += s[ii][jj];
            }
#pragma unroll
            for (int msk = 1; msk < 16; msk <<= 1)
                sum += __shfl_xor_sync(0xffffffffu, sum, msk);
            lrow[ii] = lrow[ii] * corr + sum;
            mrow[ii] = mnew;
#pragma unroll
            for (int jj = 0; jj < 4; jj++) o[ii][jj] *= corr;
        }
        __syncthreads();   // all K-tile reads done: safe to overwrite as Pt

        // Store P transposed: Pt[kk][i]
#pragma unroll
        for (int ii = 0; ii < 4; ii++)
#pragma unroll
            for (int jj = 0; jj < 4; jj++)
                KPt[(4 * tx + jj) * 68 + 4 * ty + ii] = s[ii][jj];
        __syncthreads();

        // O += P V
#pragma unroll 8
        for (int kk = 0; kk < 64; kk++) {
            float4 pv = *(const float4*)&KPt[kk * 68 + 4 * ty];
            float4 vv = *(const float4*)&Vs[kk * 64 + 4 * tx];
            float pa[4] = {pv.x, pv.y, pv.z, pv.w};
            float va[4] = {vv.x, vv.y, vv.z, vv.w};
#pragma unroll
            for (int ii = 0; ii < 4; ii++)
#pragma unroll
                for (int jj = 0; jj < 4; jj++)
                    o[ii][jj] = fmaf(pa[ii], va[jj], o[ii][jj]);
        }
        __syncthreads();   // before next tile's loads overwrite KPt/Vs
    }

    // Normalize and write to g_ao in [B,N,C] layout
    const int b = bh >> 4, h = bh & 15;
#pragma unroll
    for (int ii = 0; ii < 4; ii++) {
        float inv = 1.0f / lrow[ii];
        int row = q0 + 4 * ty + ii;
#pragma unroll
        for (int jj = 0; jj < 4; jj++) {
            g_ao[((size_t)b * Nn + row) * Cc + h * 64 + 4 * tx + jj] = o[ii][jj] * inv;
        }
    }
}

// ---------------------------------------------------------------------------
extern "C" void kernel_launch(void* const* d_in, const int* in_sizes, int n_in,
                              void* d_out, int out_size)
{
    const float* x     = (const float*)d_in[0];
    const float* w_in  = (const float*)d_in[1];
    const float* b_in  = (const float*)d_in[2];
    const float* w_out = (const float*)d_in[3];
    const float* b_out = (const float*)d_in[4];
    float* out = (float*)d_out;

    cudaFuncSetAttribute(attn_kernel,
                         cudaFuncAttributeMaxDynamicSharedMemorySize, 51200);

    // QKV projection: 8192 x 3072 x 1024
    gemm_tn<0><<<dim3(48, 64), 256>>>(x, w_in, b_in, nullptr);
    // Attention: 128 (b,h) x 16 q-tiles
    attn_kernel<<<dim3(16, 128), 256, 51200>>>();
    // Output projection: 8192 x 1024 x 1024
    gemm_tn<1><<<dim3(16, 64), 256>>>(nullptr, w_out, b_out, out);
}

// round 5
// speedup vs baseline: 1.5679x; 1.5679x over previous
#include <cuda_runtime.h>
#include <cuda_bf16.h>
#include <cstdint>

#define Bb 8
#define Nn 1024
#define Cc 1024
#define Hh 16
#define Dd 64

// ---------------- scratch (device globals; allocation-free) ----------------
__device__ float g_q[Bb * Hh * Nn * Dd];    // [B,H,N,D] fp32
__device__ float g_k[Bb * Hh * Nn * Dd];
__device__ float g_v[Bb * Hh * Nn * Dd];

__device__ __align__(16) __nv_bfloat16 g_xh[Bb * Nn * Cc];   // x hi/lo
__device__ __align__(16) __nv_bfloat16 g_xl[Bb * Nn * Cc];
__device__ __align__(16) __nv_bfloat16 g_wih[3 * Cc * Cc];   // w_in hi/lo
__device__ __align__(16) __nv_bfloat16 g_wil[3 * Cc * Cc];
__device__ __align__(16) __nv_bfloat16 g_woh[Cc * Cc];       // w_out hi/lo
__device__ __align__(16) __nv_bfloat16 g_wol[Cc * Cc];
__device__ __align__(16) __nv_bfloat16 g_aoh[Bb * Nn * Cc];  // attn out hi/lo
__device__ __align__(16) __nv_bfloat16 g_aol[Bb * Nn * Cc];

// ---------------------------- PTX helpers ----------------------------------
#define LDSM4(r0, r1, r2, r3, addr)                                          \
    asm volatile("ldmatrix.sync.aligned.m8n8.x4.shared.b16 {%0,%1,%2,%3},[%4];" \
                 : "=r"(r0), "=r"(r1), "=r"(r2), "=r"(r3) : "r"(addr))
#define LDSM2(r0, r1, addr)                                                  \
    asm volatile("ldmatrix.sync.aligned.m8n8.x2.shared.b16 {%0,%1},[%2];"    \
                 : "=r"(r0), "=r"(r1) : "r"(addr))
#define MMA16816(c, a, b)                                                    \
    asm volatile("mma.sync.aligned.m16n8k16.row.col.f32.bf16.bf16.f32 "      \
                 "{%0,%1,%2,%3},{%4,%5,%6,%7},{%8,%9},{%0,%1,%2,%3};"        \
                 : "+f"((c)[0]), "+f"((c)[1]), "+f"((c)[2]), "+f"((c)[3])    \
                 : "r"((a)[0]), "r"((a)[1]), "r"((a)[2]), "r"((a)[3]),       \
                   "r"((b)[0]), "r"((b)[1]))
#define CP_ASYNC16(dst, src)                                                 \
    asm volatile("cp.async.cg.shared.global [%0],[%1],16;" :: "r"(dst), "l"(src))
#define CP_COMMIT() asm volatile("cp.async.commit_group;")
#define CP_WAIT1()  asm volatile("cp.async.wait_group 1;")
#define CP_WAIT0()  asm volatile("cp.async.wait_group 0;")

// ------------------------- fp32 -> bf16 hi/lo split -------------------------
// which: 0 = x, 1 = w_in, 2 = w_out
__global__ __launch_bounds__(256) void cvt_kernel(const float4* __restrict__ in,
                                                  int which, int n4)
{
    int i = blockIdx.x * 256 + threadIdx.x;
    if (i >= n4) return;
    __nv_bfloat16 *hi, *lo;
    if (which == 0)      { hi = g_xh;  lo = g_xl;  }
    else if (which == 1) { hi = g_wih; lo = g_wil; }
    else                 { hi = g_woh; lo = g_wol; }
    float4 f = in[i];
    __nv_bfloat16 h0 = __float2bfloat16(f.x);
    __nv_bfloat16 h1 = __float2bfloat16(f.y);
    __nv_bfloat16 h2 = __float2bfloat16(f.z);
    __nv_bfloat16 h3 = __float2bfloat16(f.w);
    __nv_bfloat16 l0 = __float2bfloat16(f.x - __bfloat162float(h0));
    __nv_bfloat16 l1 = __float2bfloat16(f.y - __bfloat162float(h1));
    __nv_bfloat16 l2 = __float2bfloat16(f.z - __bfloat162float(h2));
    __nv_bfloat16 l3 = __float2bfloat16(f.w - __bfloat162float(h3));
    ushort4 ph = make_ushort4(__bfloat16_as_ushort(h0), __bfloat16_as_ushort(h1),
                              __bfloat16_as_ushort(h2), __bfloat16_as_ushort(h3));
    ushort4 pl = make_ushort4(__bfloat16_as_ushort(l0), __bfloat16_as_ushort(l1),
                              __bfloat16_as_ushort(l2), __bfloat16_as_ushort(l3));
    ((ushort4*)hi)[i] = ph;
    ((ushort4*)lo)[i] = pl;
}

// ---------------------------------------------------------------------------
// bf16x3 TN GEMM on tensor pipe: C[m,n] = sum_k A[m,k]*W[n,k] + bias[n]
// CTA tile 128x128, BK=32, 8 warps (2m x 4n), warp tile 64x32.
// acc += Ah*Wh + Ah*Wl + Al*Wh  (fp32 accumulators in MMA).
// EPI=0: A = x(hi/lo), W = w_in(hi/lo), scatter -> g_q/g_k/g_v (fp32).
// EPI=1: A = attn out(hi/lo), W = w_out(hi/lo), write -> out (fp32).
// ---------------------------------------------------------------------------
#define LDS 40                     // padded bf16 row stride (80 B)
#define TILE_B (128 * LDS * 2)     // one tile in bytes (10240)

template <int EPI>
__device__ __forceinline__ void gemm_load_chunk(
    uint32_t sbase, int bm, int bn, int k0, int tid)
{
    const __nv_bfloat16* Ah = (EPI == 0) ? g_xh : g_aoh;
    const __nv_bfloat16* Al = (EPI == 0) ? g_xl : g_aol;
    const __nv_bfloat16* Wh = (EPI == 0) ? g_wih : g_woh;
    const __nv_bfloat16* Wl = (EPI == 0) ? g_wil : g_wol;
#pragma unroll
    for (int u = 0; u < 2; u++) {
        int idx = u * 256 + tid;          // 0..511
        int row = idx >> 2;               // 0..127
        int kg  = (idx & 3) * 8;          // bf16 col offset
        uint32_t soff = (uint32_t)(row * LDS + kg) * 2;
        size_t ga = (size_t)(bm + row) * 1024 + k0 + kg;
        size_t gw = (size_t)(bn + row) * 1024 + k0 + kg;
        CP_ASYNC16(sbase + 0 * TILE_B + soff, Ah + ga);
        CP_ASYNC16(sbase + 1 * TILE_B + soff, Al + ga);
        CP_ASYNC16(sbase + 2 * TILE_B + soff, Wh + gw);
        CP_ASYNC16(sbase + 3 * TILE_B + soff, Wl + gw);
    }
}

template <int EPI>
__global__ __launch_bounds__(256, 1) void gemm_mma(const float* __restrict__ bias,
                                                   float* __restrict__ out)
{
    extern __shared__ __align__(16) char smem[];
    const uint32_t sm0 = (uint32_t)__cvta_generic_to_shared(smem);

    const int tid  = threadIdx.x;
    const int lane = tid & 31;
    const int wid  = tid >> 5;
    const int wm = (wid & 1) * 64;        // warp m offset in CTA tile
    const int wn = (wid >> 1) * 32;       // warp n offset
    const int bm = blockIdx.y * 128;
    const int bn = blockIdx.x * 128;

    // ldmatrix lane address offsets (bytes, relative to tile base)
    const int lr = lane & 7, lq = lane >> 3;        // A: x4
    const uint32_t a_off =
        (uint32_t)(((wm + (lq & 1) * 8 + lr) * LDS + (lq >> 1) * 8) * 2);
    const int l2 = lane & 15;                       // B: x2
    const uint32_t b_off =
        (uint32_t)(((wn + (l2 & 7)) * LDS + (l2 >> 3) * 8) * 2);

    float c[4][4][4];
#pragma unroll
    for (int im = 0; im < 4; im++)
#pragma unroll
        for (int in = 0; in < 4; in++)
#pragma unroll
            for (int q = 0; q < 4; q++) c[im][in][q] = 0.0f;

    // prologue: chunk 0 -> stage 0
    gemm_load_chunk<EPI>(sm0, bm, bn, 0, tid);
    CP_COMMIT();

    for (int cidx = 0; cidx < 32; cidx++) {
        if (cidx < 31) {
            gemm_load_chunk<EPI>(sm0 + ((cidx + 1) & 1) * 4 * TILE_B,
                                 bm, bn, (cidx + 1) * 32, tid);
            CP_COMMIT();
            CP_WAIT1();
        } else {
            CP_WAIT0();
        }
        __syncthreads();

        const uint32_t st = sm0 + (cidx & 1) * 4 * TILE_B;
        const uint32_t tAh = st, tAl = st + TILE_B;
        const uint32_t tBh = st + 2 * TILE_B, tBl = st + 3 * TILE_B;

#pragma unroll
        for (int ks = 0; ks < 2; ks++) {
            uint32_t aH[4][4], aL[4][4], bH[4][2], bL[4][2];
#pragma unroll
            for (int im = 0; im < 4; im++) {
                uint32_t off = a_off + (uint32_t)(im * 16 * LDS * 2 + ks * 32);
                LDSM4(aH[im][0], aH[im][1], aH[im][2], aH[im][3], tAh + off);
                LDSM4(aL[im][0], aL[im][1], aL[im][2], aL[im][3], tAl + off);
            }
#pragma unroll
            for (int in = 0; in < 4; in++) {
                uint32_t off = b_off + (uint32_t)(in * 8 * LDS * 2 + ks * 32);
                LDSM2(bH[in][0], bH[in][1], tBh + off);
                LDSM2(bL[in][0], bL[in][1], tBl + off);
            }
#pragma unroll
            for (int in = 0; in < 4; in++)
#pragma unroll
                for (int im = 0; im < 4; im++) {
                    MMA16816(c[im][in], aH[im], bH[in]);
                    MMA16816(c[im][in], aH[im], bL[in]);
                    MMA16816(c[im][in], aL[im], bH[in]);
                }
        }
        __syncthreads();
    }

    // epilogue
#pragma unroll
    for (int im = 0; im < 4; im++) {
#pragma unroll
        for (int in = 0; in < 4; in++) {
            int r0 = bm + wm + im * 16 + (lane >> 2);
            int cg = bn + wn + in * 8 + 2 * (lane & 3);
            float b0 = bias[cg], b1 = bias[cg + 1];
#pragma unroll
            for (int half = 0; half < 2; half++) {
                int r = r0 + half * 8;
                float2 v = make_float2(c[im][in][half * 2 + 0] + b0,
                                       c[im][in][half * 2 + 1] + b1);
                if (EPI == 0) {
                    int b = r >> 10, nn = r & 1023;
                    int s = cg >> 10;
                    int h = (cg >> 6) & 15;
                    int d = cg & 63;
                    float* dst = (s == 0) ? g_q : (s == 1) ? g_k : g_v;
                    *(float2*)&dst[(((size_t)b * Hh + h) * Nn + nn) * Dd + d] = v;
                } else {
                    *(float2*)&out[(size_t)r * 1024 + cg] = v;
                }
            }
        }
    }
}

// ---------------------------------------------------------------------------
// Flash attention (fp32, unchanged math). Epilogue now writes bf16 hi/lo
// attention output directly (feeds the bf16x3 out-projection).
// ---------------------------------------------------------------------------
__global__ __launch_bounds__(256) void attn_kernel()
{
    extern __shared__ __align__(16) float sm[];
    float* Qt  = sm;                  // Qt[d*68 + i]
    float* KPt = sm + 64 * 68;        // Kt[d*68 + j]  /  Pt[kk*68 + i]
    float* Vs  = sm + 2 * 64 * 68;    // Vs[kk*64 + d]

    const int tid = threadIdx.x;
    const int tx = tid & 15;
    const int ty = tid >> 4;
    const int bh = blockIdx.y;        // b*16 + h
    const int q0 = blockIdx.x * 64;

    const float* Qp = g_q + (size_t)bh * Nn * Dd;
    const float* Kp = g_k + (size_t)bh * Nn * Dd;
    const float* Vp = g_v + (size_t)bh * Nn * Dd;
    const float scale = 0.125f;

#pragma unroll
    for (int u = 0; u < 4; u++) {
        int i = tid + u * 256;
        int row = i >> 4, c = i & 15;
        float4 f = *(const float4*)(Qp + (size_t)(q0 + row) * 64 + 4 * c);
        Qt[(4 * c + 0) * 68 + row] = f.x * scale;
        Qt[(4 * c + 1) * 68 + row] = f.y * scale;
        Qt[(4 * c + 2) * 68 + row] = f.z * scale;
        Qt[(4 * c + 3) * 68 + row] = f.w * scale;
    }
    __syncthreads();

    float o[4][4];
    float mrow[4], lrow[4];
#pragma unroll
    for (int ii = 0; ii < 4; ii++) {
        mrow[ii] = -1e30f;
        lrow[ii] = 0.0f;
#pragma unroll
        for (int jj = 0; jj < 4; jj++) o[ii][jj] = 0.0f;
    }

    for (int t = 0; t < 16; t++) {
        const float* Kt0 = Kp + (size_t)t * 64 * 64;
        const float* Vt0 = Vp + (size_t)t * 64 * 64;
#pragma unroll
        for (int u = 0; u < 4; u++) {
            int i = tid + u * 256;
            int row = i >> 4, c = i & 15;
            float4 f = *(const float4*)(Kt0 + (size_t)row * 64 + 4 * c);
            KPt[(4 * c + 0) * 68 + row] = f.x;
            KPt[(4 * c + 1) * 68 + row] = f.y;
            KPt[(4 * c + 2) * 68 + row] = f.z;
            KPt[(4 * c + 3) * 68 + row] = f.w;
            float4 g = *(const float4*)(Vt0 + (size_t)row * 64 + 4 * c);
            *(float4*)&Vs[row * 64 + 4 * c] = g;
        }
        __syncthreads();

        float s[4][4];
#pragma unroll
        for (int ii = 0; ii < 4; ii++)
#pragma unroll
            for (int jj = 0; jj < 4; jj++) s[ii][jj] = 0.0f;

#pragma unroll 8
        for (int d = 0; d < 64; d++) {
            float4 qv = *(const float4*)&Qt[d * 68 + 4 * ty];
            float4 kv = *(const float4*)&KPt[d * 68 + 4 * tx];
            float qa[4] = {qv.x, qv.y, qv.z, qv.w};
            float ka[4] = {kv.x, kv.y, kv.z, kv.w};
#pragma unroll
            for (int ii = 0; ii < 4; ii++)
#pragma unroll
                for (int jj = 0; jj < 4; jj++)
                    s[ii][jj] = fmaf(qa[ii], ka[jj], s[ii][jj]);
        }

#pragma unroll
        for (int ii = 0; ii < 4; ii++) {
            float mx = fmaxf(fmaxf(s[ii][0], s[ii][1]), fmaxf(s[ii][2], s[ii][3]));
#pragma unroll
            for (int msk = 1; msk < 16; msk <<= 1)
                mx = fmaxf(mx, __shfl_xor_sync(0xffffffffu, mx, msk));
            float mnew = fmaxf(mrow[ii], mx);
            float corr = __expf(mrow[ii] - mnew);
            float sum = 0.0f;
#pragma unroll
            for (int jj = 0; jj < 4; jj++) {
                s[ii][jj] = __expf(s[ii][jj] - mnew);
                sum += s[ii][jj];
            }
#pragma unroll
            for (int msk = 1; msk < 16; msk <<= 1)
                sum += __shfl_xor_sync(0xffffffffu, sum, msk);
            lrow[ii] = lrow[ii] * corr + sum;
            mrow[ii] = mnew;
#pragma unroll
            for (int jj = 0; jj < 4; jj++) o[ii][jj] *= corr;
        }
        __syncthreads();

#pragma unroll
        for (int ii = 0; ii < 4; ii++)
#pragma unroll
            for (int jj = 0; jj < 4; jj++)
                KPt[(4 * tx + jj) * 68 + 4 * ty + ii] = s[ii][jj];
        __syncthreads();

#pragma unroll 8
        for (int kk = 0; kk < 64; kk++) {
            float4 pv = *(const float4*)&KPt[kk * 68 + 4 * ty];
            float4 vv = *(const float4*)&Vs[kk * 64 + 4 * tx];
            float pa[4] = {pv.x, pv.y, pv.z, pv.w};
            float va[4] = {vv.x, vv.y, vv.z, vv.w};
#pragma unroll
            for (int ii = 0; ii < 4; ii++)
#pragma unroll
                for (int jj = 0; jj < 4; jj++)
                    o[ii][jj] = fmaf(pa[ii], va[jj], o[ii][jj]);
        }
        __syncthreads();
    }

    // normalize, split to bf16 hi/lo, write [B,N,C]
    const int b = bh >> 4, h = bh & 15;
#pragma unroll
    for (int ii = 0; ii < 4; ii++) {
        float inv = 1.0f / lrow[ii];
        int row = q0 + 4 * ty + ii;
#pragma unroll
        for (int jj = 0; jj < 4; jj++) {
            float v = o[ii][jj] * inv;
            size_t idx = ((size_t)b * Nn + row) * Cc + h * 64 + 4 * tx + jj;
            __nv_bfloat16 hv = __float2bfloat16(v);
            g_aoh[idx] = hv;
            g_aol[idx] = __float2bfloat16(v - __bfloat162float(hv));
        }
    }
}

// ---------------------------------------------------------------------------
extern "C" void kernel_launch(void* const* d_in, const int* in_sizes, int n_in,
                              void* d_out, int out_size)
{
    const float* x     = (const float*)d_in[0];
    const float* b_in  = (const float*)d_in[2];
    const float* w_in  = (const float*)d_in[1];
    const float* w_out = (const float*)d_in[3];
    const float* b_out = (const float*)d_in[4];
    float* out = (float*)d_out;

    static bool attr_done = false;
    cudaFuncSetAttribute(attn_kernel,
                         cudaFuncAttributeMaxDynamicSharedMemorySize, 51200);
    cudaFuncSetAttribute(gemm_mma<0>,
                         cudaFuncAttributeMaxDynamicSharedMemorySize, 81920);
    cudaFuncSetAttribute(gemm_mma<1>,
                         cudaFuncAttributeMaxDynamicSharedMemorySize, 81920);
    (void)attr_done;

    // fp32 -> bf16 hi/lo splits
    cvt_kernel<<<(Bb * Nn * Cc / 4 + 255) / 256, 256>>>((const float4*)x, 0, Bb * Nn * Cc / 4);
    cvt_kernel<<<(3 * Cc * Cc / 4 + 255) / 256, 256>>>((const float4*)w_in, 1, 3 * Cc * Cc / 4);
    cvt_kernel<<<(Cc * Cc / 4 + 255) / 256, 256>>>((const float4*)w_out, 2, Cc * Cc / 4);

    // QKV projection: 8192 x 3072 x 1024 (bf16x3 tensor-pipe)
    gemm_mma<0><<<dim3(24, 64), 256, 81920>>>(b_in, nullptr);
    // Attention: 128 (b,h) x 16 q-tiles (fp32)
    attn_kernel<<<dim3(16, 128), 256, 51200>>>();
    // Output projection: 8192 x 1024 x 1024 (bf16x3 tensor-pipe)
    gemm_mma<1><<<dim3(8, 64), 256, 81920>>>(b_out, out);
}

// round 6
// speedup vs baseline: 2.6358x; 1.6811x over previous
#include <cuda_runtime.h>
#include <cuda_bf16.h>
#include <cstdint>

#define Bb 8
#define Nn 1024
#define Cc 1024
#define Hh 16
#define Dd 64
#define NDh (Nn * Dd)

// ---------------- scratch (device globals; allocation-free) ----------------
__device__ __align__(16) __nv_bfloat16 g_xh[Bb * Nn * Cc], g_xl[Bb * Nn * Cc];
__device__ __align__(16) __nv_bfloat16 g_wih[3 * Cc * Cc], g_wil[3 * Cc * Cc];
__device__ __align__(16) __nv_bfloat16 g_woh[Cc * Cc], g_wol[Cc * Cc];
__device__ __align__(16) __nv_bfloat16 g_qh[Bb * Hh * NDh], g_ql[Bb * Hh * NDh];
__device__ __align__(16) __nv_bfloat16 g_kh[Bb * Hh * NDh], g_kl[Bb * Hh * NDh];
__device__ __align__(16) __nv_bfloat16 g_vh[Bb * Hh * NDh], g_vl[Bb * Hh * NDh];
__device__ __align__(16) __nv_bfloat16 g_aoh[Bb * Nn * Cc], g_aol[Bb * Nn * Cc];

// ---------------------------- PTX helpers ----------------------------------
#define LDSM4(r0, r1, r2, r3, addr)                                          \
    asm volatile("ldmatrix.sync.aligned.m8n8.x4.shared.b16 {%0,%1,%2,%3},[%4];" \
                 : "=r"(r0), "=r"(r1), "=r"(r2), "=r"(r3) : "r"(addr))
#define LDSM4T(r0, r1, r2, r3, addr)                                         \
    asm volatile("ldmatrix.sync.aligned.m8n8.x4.trans.shared.b16 {%0,%1,%2,%3},[%4];" \
                 : "=r"(r0), "=r"(r1), "=r"(r2), "=r"(r3) : "r"(addr))
#define MMA16816(c, a, b)                                                    \
    asm volatile("mma.sync.aligned.m16n8k16.row.col.f32.bf16.bf16.f32 "      \
                 "{%0,%1,%2,%3},{%4,%5,%6,%7},{%8,%9},{%0,%1,%2,%3};"        \
                 : "+f"((c)[0]), "+f"((c)[1]), "+f"((c)[2]), "+f"((c)[3])    \
                 : "r"((a)[0]), "r"((a)[1]), "r"((a)[2]), "r"((a)[3]),       \
                   "r"((b)[0]), "r"((b)[1]))
#define CP_ASYNC16(dst, src)                                                 \
    asm volatile("cp.async.cg.shared.global [%0],[%1],16;" :: "r"(dst), "l"(src))
#define CP_COMMIT() asm volatile("cp.async.commit_group;")
#define CP_WAIT2()  asm volatile("cp.async.wait_group 2;")
#define CP_WAIT1()  asm volatile("cp.async.wait_group 1;")
#define CP_WAIT0()  asm volatile("cp.async.wait_group 0;")

__device__ __forceinline__ uint32_t packbf(float lo, float hi) {
    uint32_t r;
    asm("cvt.rn.bf16x2.f32 %0,%1,%2;" : "=r"(r) : "f"(hi), "f"(lo));
    return r;
}
// split (v0,v1) -> packed hi pair + packed lo pair
__device__ __forceinline__ void split2(float v0, float v1,
                                       uint32_t& hi, uint32_t& lo) {
    __nv_bfloat16 h0 = __float2bfloat16(v0), h1 = __float2bfloat16(v1);
    hi = ((uint32_t)__bfloat16_as_ushort(h1) << 16) | __bfloat16_as_ushort(h0);
    lo = packbf(v0 - __bfloat162float(h0), v1 - __bfloat162float(h1));
}

// ------------------------- fp32 -> bf16 hi/lo split -------------------------
__global__ __launch_bounds__(256) void cvt_kernel(const float4* __restrict__ in,
                                                  int which, int n4)
{
    int i = blockIdx.x * 256 + threadIdx.x;
    if (i >= n4) return;
    __nv_bfloat16 *hi, *lo;
    if (which == 0)      { hi = g_xh;  lo = g_xl;  }
    else if (which == 1) { hi = g_wih; lo = g_wil; }
    else                 { hi = g_woh; lo = g_wol; }
    float4 f = in[i];
    uint32_t h01, l01, h23, l23;
    split2(f.x, f.y, h01, l01);
    split2(f.z, f.w, h23, l23);
    ((uint2*)hi)[i] = make_uint2(h01, h23);
    ((uint2*)lo)[i] = make_uint2(l01, l23);
}

// ---------------------------------------------------------------------------
// bf16x3 TN GEMM (tensor pipe): C[m,n] = sum_k A[m,k]*W[n,k] + bias[n]
// CTA tile 128x128, BK=32, 3-stage cp.async, 8 warps, warp tile 64x32.
// EPI=0: A=x(hi/lo), W=w_in(hi/lo); scatter q/k/v as bf16 hi/lo (q scaled).
// EPI=1: A=attn-out(hi/lo), W=w_out(hi/lo); write fp32 out.
// ---------------------------------------------------------------------------
#define LDS 40                     // padded bf16 row stride (80 B)
#define TILE_B (128 * LDS * 2)     // 10240 B
#define SSTG (4 * TILE_B)          // 40960 B per stage

template <int EPI>
__device__ __forceinline__ void gemm_load_chunk(
    uint32_t sbase, int bm, int bn, int k0, int tid)
{
    const __nv_bfloat16* Ah = (EPI == 0) ? g_xh : g_aoh;
    const __nv_bfloat16* Al = (EPI == 0) ? g_xl : g_aol;
    const __nv_bfloat16* Wh = (EPI == 0) ? g_wih : g_woh;
    const __nv_bfloat16* Wl = (EPI == 0) ? g_wil : g_wol;
#pragma unroll
    for (int u = 0; u < 2; u++) {
        int idx = u * 256 + tid;
        int row = idx >> 2;
        int kg  = (idx & 3) * 8;
        uint32_t soff = (uint32_t)(row * LDS + kg) * 2;
        size_t ga = (size_t)(bm + row) * 1024 + k0 + kg;
        size_t gw = (size_t)(bn + row) * 1024 + k0 + kg;
        CP_ASYNC16(sbase + 0 * TILE_B + soff, Ah + ga);
        CP_ASYNC16(sbase + 1 * TILE_B + soff, Al + ga);
        CP_ASYNC16(sbase + 2 * TILE_B + soff, Wh + gw);
        CP_ASYNC16(sbase + 3 * TILE_B + soff, Wl + gw);
    }
}

template <int EPI>
__global__ __launch_bounds__(256, 1) void gemm_mma(const float* __restrict__ bias,
                                                   float* __restrict__ out)
{
    extern __shared__ __align__(16) char smem[];
    const uint32_t sm0 = (uint32_t)__cvta_generic_to_shared(smem);

    const int tid  = threadIdx.x;
    const int lane = tid & 31;
    const int wid  = tid >> 5;
    const int wm = (wid & 1) * 64;
    const int wn = (wid >> 1) * 32;
    const int bm = blockIdx.y * 128;
    const int bn = blockIdx.x * 128;

    const int lr = lane & 7, lq = lane >> 3;
    const uint32_t a_off =
        (uint32_t)(((wm + (lq & 1) * 8 + lr) * LDS + (lq >> 1) * 8) * 2);
    const int l2 = lane & 15;
    const uint32_t b_off =
        (uint32_t)(((wn + (l2 & 7)) * LDS + (l2 >> 3) * 8) * 2);

    float c[4][4][4];
#pragma unroll
    for (int im = 0; im < 4; im++)
#pragma unroll
        for (int in = 0; in < 4; in++)
#pragma unroll
            for (int q = 0; q < 4; q++) c[im][in][q] = 0.0f;

    gemm_load_chunk<EPI>(sm0 + 0 * SSTG, bm, bn, 0, tid);
    CP_COMMIT();
    gemm_load_chunk<EPI>(sm0 + 1 * SSTG, bm, bn, 32, tid);
    CP_COMMIT();

    for (int cidx = 0; cidx < 32; cidx++) {
        if (cidx < 30) {
            gemm_load_chunk<EPI>(sm0 + ((cidx + 2) % 3) * SSTG,
                                 bm, bn, (cidx + 2) * 32, tid);
            CP_COMMIT();
            CP_WAIT2();
        } else if (cidx == 30) {
            CP_WAIT1();
        } else {
            CP_WAIT0();
        }
        __syncthreads();

        const uint32_t st = sm0 + (cidx % 3) * SSTG;
        const uint32_t tAh = st, tAl = st + TILE_B;
        const uint32_t tBh = st + 2 * TILE_B, tBl = st + 3 * TILE_B;

#pragma unroll
        for (int ks = 0; ks < 2; ks++) {
            uint32_t aH[4][4], aL[4][4], bH[4][2], bL[4][2];
#pragma unroll
            for (int im = 0; im < 4; im++) {
                uint32_t off = a_off + (uint32_t)(im * 16 * LDS * 2 + ks * 32);
                LDSM4(aH[im][0], aH[im][1], aH[im][2], aH[im][3], tAh + off);
                LDSM4(aL[im][0], aL[im][1], aL[im][2], aL[im][3], tAl + off);
            }
#pragma unroll
            for (int in = 0; in < 4; in++) {
                uint32_t off = b_off + (uint32_t)(in * 8 * LDS * 2 + ks * 32);
                asm volatile("ldmatrix.sync.aligned.m8n8.x2.shared.b16 {%0,%1},[%2];"
                             : "=r"(bH[in][0]), "=r"(bH[in][1]) : "r"(tBh + off));
                asm volatile("ldmatrix.sync.aligned.m8n8.x2.shared.b16 {%0,%1},[%2];"
                             : "=r"(bL[in][0]), "=r"(bL[in][1]) : "r"(tBl + off));
            }
#pragma unroll
            for (int in = 0; in < 4; in++)
#pragma unroll
                for (int im = 0; im < 4; im++) {
                    MMA16816(c[im][in], aH[im], bH[in]);
                    MMA16816(c[im][in], aH[im], bL[in]);
                    MMA16816(c[im][in], aL[im], bH[in]);
                }
        }
        __syncthreads();
    }

    // epilogue
#pragma unroll
    for (int im = 0; im < 4; im++) {
#pragma unroll
        for (int in = 0; in < 4; in++) {
            int r0 = bm + wm + im * 16 + (lane >> 2);
            int cg = bn + wn + in * 8 + 2 * (lane & 3);
            float b0 = bias[cg], b1 = bias[cg + 1];
#pragma unroll
            for (int half = 0; half < 2; half++) {
                int r = r0 + half * 8;
                float v0 = c[im][in][half * 2 + 0] + b0;
                float v1 = c[im][in][half * 2 + 1] + b1;
                if (EPI == 0) {
                    int b = r >> 10, nn = r & 1023;
                    int s = cg >> 10;
                    int h = (cg >> 6) & 15;
                    int d = cg & 63;
                    if (s == 0) { v0 *= 0.125f; v1 *= 0.125f; }  // fold QK scale
                    __nv_bfloat16 *hiA = (s == 0) ? g_qh : (s == 1) ? g_kh : g_vh;
                    __nv_bfloat16 *loA = (s == 0) ? g_ql : (s == 1) ? g_kl : g_vl;
                    size_t idx = (((size_t)b * Hh + h) * Nn + nn) * Dd + d;
                    uint32_t hp, lp;
                    split2(v0, v1, hp, lp);
                    *(uint32_t*)&hiA[idx] = hp;
                    *(uint32_t*)&loA[idx] = lp;
                } else {
                    *(float2*)&out[(size_t)r * 1024 + cg] = make_float2(v0, v1);
                }
            }
        }
    }
}

// ---------------------------------------------------------------------------
// MMA flash attention. CTA = 128 Q rows x one (b,h); 8 warps, each warp owns
// 16 Q rows x all keys. Key tiles of 64, double-buffered cp.async.
// S = Qh*Kh + Qh*Kl + Ql*Kh (fp32 acc); softmax fp32 in C-fragment layout;
// P re-split hi/lo in registers; O += Ph*Vh + Ph*Vl + Pl*Vh.
// Smem/stage: Kh,Kl,Vh,Vl each 64 rows x stride 72 bf16 (9216 B) = 36864 B;
// 2 stages = 73728 B. Q staged through stage 1 before the main loop.
// ---------------------------------------------------------------------------
#define ASTG 36864
#define AMAT 9216

__global__ __launch_bounds__(256, 1) void attn_mma()
{
    extern __shared__ __align__(16) char smem[];
    const uint32_t sm0 = (uint32_t)__cvta_generic_to_shared(smem);

    const int tid  = threadIdx.x;
    const int lane = tid & 31;
    const int wq   = tid >> 5;          // warp 0..7 -> q rows wq*16..
    const int bh = blockIdx.y;
    const int q0 = blockIdx.x * 128;

    const __nv_bfloat16* Qhp = g_qh + (size_t)bh * NDh;
    const __nv_bfloat16* Qlp = g_ql + (size_t)bh * NDh;
    const __nv_bfloat16* Khp = g_kh + (size_t)bh * NDh;
    const __nv_bfloat16* Klp = g_kl + (size_t)bh * NDh;
    const __nv_bfloat16* Vhp = g_vh + (size_t)bh * NDh;
    const __nv_bfloat16* Vlp = g_vl + (size_t)bh * NDh;

    // ---- stage Q through stage-1 region; prefetch KV tile 0 into stage 0 --
    const uint32_t qbase = sm0 + ASTG;
#pragma unroll
    for (int u = 0; u < 8; u++) {
        const __nv_bfloat16* mp = (u < 4) ? Qhp : Qlp;
        int r = (u & 3) * 32 + (tid >> 3);
        int cc = tid & 7;
        CP_ASYNC16(qbase + (u >> 2) * (128 * 144) + r * 144 + cc * 16,
                   mp + (size_t)(q0 + r) * 64 + cc * 8);
    }
    CP_COMMIT();
    {
#pragma unroll
        for (int u = 0; u < 8; u++) {
            const __nv_bfloat16* mp = (u < 2) ? Khp : (u < 4) ? Klp
                                     : (u < 6) ? Vhp : Vlp;
            int r = (u & 1) * 32 + (tid >> 3);
            int cc = tid & 7;
            CP_ASYNC16(sm0 + (u >> 1) * AMAT + r * 144 + cc * 16,
                       mp + (size_t)r * 64 + cc * 8);
        }
        CP_COMMIT();
    }
    CP_WAIT1();            // Q staged (KV0 may still be in flight)
    __syncthreads();

    // ---- Q fragments to registers (held for the whole kernel) -------------
    uint32_t qfh[4][4], qfl[4][4];
    {
        const int lr = lane & 7, lq = lane >> 3;
        uint32_t qa = qbase + (uint32_t)((wq * 16 + (lq & 1) * 8 + lr) * 144
                                         + (lq >> 1) * 16);
#pragma unroll
        for (int ks = 0; ks < 4; ks++) {
            LDSM4(qfh[ks][0], qfh[ks][1], qfh[ks][2], qfh[ks][3], qa + ks * 32);
            LDSM4(qfl[ks][0], qfl[ks][1], qfl[ks][2], qfl[ks][3],
                  qa + 128 * 144 + ks * 32);
        }
    }
    __syncthreads();       // Q smem region may now be reused as stage 1

    float o[8][4];
    float mrow[2] = {-1e30f, -1e30f}, lrow[2] = {0.0f, 0.0f};
#pragma unroll
    for (int j = 0; j < 8; j++)
#pragma unroll
        for (int q = 0; q < 4; q++) o[j][q] = 0.0f;

    for (int t = 0; t < 16; t++) {
        if (t < 15) {      // prefetch next tile into the other stage
            uint32_t nb = sm0 + ((t + 1) & 1) * ASTG;
            int key0 = (t + 1) * 64;
#pragma unroll
            for (int u = 0; u < 8; u++) {
                const __nv_bfloat16* mp = (u < 2) ? Khp : (u < 4) ? Klp
                                         : (u < 6) ? Vhp : Vlp;
                int r = (u & 1) * 32 + (tid >> 3);
                int cc = tid & 7;
                CP_ASYNC16(nb + (u >> 1) * AMAT + r * 144 + cc * 16,
                           mp + (size_t)(key0 + r) * 64 + cc * 8);
            }
            CP_COMMIT();
            CP_WAIT1();
        } else {
            CP_WAIT0();
        }
        __syncthreads();

        const uint32_t st = sm0 + (t & 1) * ASTG;

        // ---- S = Q K^T -----------------------------------------------------
        float s[8][4];
#pragma unroll
        for (int j = 0; j < 8; j++)
#pragma unroll
            for (int q = 0; q < 4; q++) s[j][q] = 0.0f;

        const uint32_t kaddr = st + (uint32_t)(((lane & 7) + ((lane >> 4) & 1) * 8) * 144
                                               + ((lane >> 3) & 1) * 16);
#pragma unroll
        for (int ks = 0; ks < 4; ks++) {
            uint32_t kh[4][4], kl[4][4];
#pragma unroll
            for (int jn2 = 0; jn2 < 4; jn2++) {
                uint32_t off = kaddr + (uint32_t)(jn2 * 16 * 144 + ks * 32);
                LDSM4(kh[jn2][0], kh[jn2][1], kh[jn2][2], kh[jn2][3], off);
                LDSM4(kl[jn2][0], kl[jn2][1], kl[jn2][2], kl[jn2][3], off + AMAT);
            }
#pragma unroll
            for (int jn2 = 0; jn2 < 4; jn2++) {
                MMA16816(s[2 * jn2],     qfh[ks], &kh[jn2][0]);
                MMA16816(s[2 * jn2],     qfh[ks], &kl[jn2][0]);
                MMA16816(s[2 * jn2],     qfl[ks], &kh[jn2][0]);
                MMA16816(s[2 * jn2 + 1], qfh[ks], &kh[jn2][2]);
                MMA16816(s[2 * jn2 + 1], qfh[ks], &kl[jn2][2]);
                MMA16816(s[2 * jn2 + 1], qfl[ks], &kh[jn2][2]);
            }
        }

        // ---- online softmax (rows lane>>2 and +8; cols across quad lanes) --
#pragma unroll
        for (int r = 0; r < 2; r++) {
            float mx = -1e30f;
#pragma unroll
            for (int j = 0; j < 8; j++)
                mx = fmaxf(mx, fmaxf(s[j][2 * r], s[j][2 * r + 1]));
            mx = fmaxf(mx, __shfl_xor_sync(0xffffffffu, mx, 1));
            mx = fmaxf(mx, __shfl_xor_sync(0xffffffffu, mx, 2));
            float mnew = fmaxf(mrow[r], mx);
            float corr = __expf(mrow[r] - mnew);
            float sum = 0.0f;
#pragma unroll
            for (int j = 0; j < 8; j++) {
                s[j][2 * r]     = __expf(s[j][2 * r]     - mnew);
                s[j][2 * r + 1] = __expf(s[j][2 * r + 1] - mnew);
                sum += s[j][2 * r] + s[j][2 * r + 1];
            }
            sum += __shfl_xor_sync(0xffffffffu, sum, 1);
            sum += __shfl_xor_sync(0xffffffffu, sum, 2);
            lrow[r] = lrow[r] * corr + sum;
            mrow[r] = mnew;
#pragma unroll
            for (int j = 0; j < 8; j++) {
                o[j][2 * r]     *= corr;
                o[j][2 * r + 1] *= corr;
            }
        }

        // ---- O += P V ------------------------------------------------------
        const uint32_t vaddr = st + 2 * AMAT
            + (uint32_t)((lane & 15) * 144 + (lane >> 4) * 16);
#pragma unroll
        for (int ks2 = 0; ks2 < 4; ks2++) {
            // repack S C-frags (tiles 2ks2, 2ks2+1) into A-frags, hi/lo split
            uint32_t pah[4], pal[4];
            float* s0 = s[2 * ks2];
            float* s1 = s[2 * ks2 + 1];
            split2(s0[0], s0[1], pah[0], pal[0]);
            split2(s0[2], s0[3], pah[1], pal[1]);
            split2(s1[0], s1[1], pah[2], pal[2]);
            split2(s1[2], s1[3], pah[3], pal[3]);

            uint32_t vrow = vaddr + (uint32_t)(ks2 * 16 * 144);
#pragma unroll
            for (int jd2 = 0; jd2 < 4; jd2++) {
                uint32_t vh[4], vl[4];
                uint32_t off = vrow + (uint32_t)(jd2 * 32);
                LDSM4T(vh[0], vh[1], vh[2], vh[3], off);
                LDSM4T(vl[0], vl[1], vl[2], vl[3], off + AMAT);
                MMA16816(o[2 * jd2],     pah, &vh[0]);
                MMA16816(o[2 * jd2],     pah, &vl[0]);
                MMA16816(o[2 * jd2],     pal, &vh[0]);
                MMA16816(o[2 * jd2 + 1], pah, &vh[2]);
                MMA16816(o[2 * jd2 + 1], pah, &vl[2]);
                MMA16816(o[2 * jd2 + 1], pal, &vh[2]);
            }
        }
        __syncthreads();   // all reads of stage t done before it is reloaded
    }

    // ---- normalize + write bf16 hi/lo attention output [B,N,C] ------------
    const int b = bh >> 4, h = bh & 15;
    const int G = lane >> 2, T = lane & 3;
#pragma unroll
    for (int r = 0; r < 2; r++) {
        float inv = 1.0f / lrow[r];
        int row = q0 + wq * 16 + G + r * 8;
        size_t base = ((size_t)b * Nn + row) * Cc + h * 64;
#pragma unroll
        for (int jd = 0; jd < 8; jd++) {
            float v0 = o[jd][2 * r] * inv;
            float v1 = o[jd][2 * r + 1] * inv;
            int col = jd * 8 + 2 * T;
            uint32_t hp, lp;
            split2(v0, v1, hp, lp);
            *(uint32_t*)&g_aoh[base + col] = hp;
            *(uint32_t*)&g_aol[base + col] = lp;
        }
    }
}

// ---------------------------------------------------------------------------
extern "C" void kernel_launch(void* const* d_in, const int* in_sizes, int n_in,
                              void* d_out, int out_size)
{
    const float* x     = (const float*)d_in[0];
    const float* w_in  = (const float*)d_in[1];
    const float* b_in  = (const float*)d_in[2];
    const float* w_out = (const float*)d_in[3];
    const float* b_out = (const float*)d_in[4];
    float* out = (float*)d_out;

    cudaFuncSetAttribute(gemm_mma<0>,
                         cudaFuncAttributeMaxDynamicSharedMemorySize, 3 * SSTG);
    cudaFuncSetAttribute(gemm_mma<1>,
                         cudaFuncAttributeMaxDynamicSharedMemorySize, 3 * SSTG);
    cudaFuncSetAttribute(attn_mma,
                         cudaFuncAttributeMaxDynamicSharedMemorySize, 2 * ASTG);

    // fp32 -> bf16 hi/lo splits
    cvt_kernel<<<(Bb * Nn * Cc / 4 + 255) / 256, 256>>>((const float4*)x, 0, Bb * Nn * Cc / 4);
    cvt_kernel<<<(3 * Cc * Cc / 4 + 255) / 256, 256>>>((const float4*)w_in, 1, 3 * Cc * Cc / 4);
    cvt_kernel<<<(Cc * Cc / 4 + 255) / 256, 256>>>((const float4*)w_out, 2, Cc * Cc / 4);

    // QKV projection: 8192 x 3072 x 1024 -> bf16 hi/lo q/k/v (q pre-scaled)
    gemm_mma<0><<<dim3(24, 64), 256, 3 * SSTG>>>(b_in, nullptr);
    // Attention: 8 q-tiles x 128 (b,h), tensor-pipe flash attention
    attn_mma<<<dim3(8, 128), 256, 2 * ASTG>>>();
    // Output projection: 8192 x 1024 x 1024
    gemm_mma<1><<<dim3(8, 64), 256, 3 * SSTG>>>(b_out, out);
}

// round 8
// speedup vs baseline: 2.7464x; 1.0419x over previous
#include <cuda_runtime.h>
#include <cuda_bf16.h>
#include <cstdint>

#define Bb 8
#define Nn 1024
#define Cc 1024
#define Hh 16
#define Dd 64
#define NDh (Nn * Dd)

// ---------------- scratch (device globals; allocation-free) ----------------
__device__ __align__(16) __nv_bfloat16 g_xh[Bb * Nn * Cc], g_xl[Bb * Nn * Cc];
__device__ __align__(16) __nv_bfloat16 g_wih[3 * Cc * Cc], g_wil[3 * Cc * Cc];
__device__ __align__(16) __nv_bfloat16 g_woh[Cc * Cc], g_wol[Cc * Cc];
__device__ __align__(16) __nv_bfloat16 g_qh[Bb * Hh * NDh], g_ql[Bb * Hh * NDh];
__device__ __align__(16) __nv_bfloat16 g_kh[Bb * Hh * NDh], g_kl[Bb * Hh * NDh];
__device__ __align__(16) __nv_bfloat16 g_vh[Bb * Hh * NDh], g_vl[Bb * Hh * NDh];
__device__ __align__(16) __nv_bfloat16 g_aoh[Bb * Nn * Cc], g_aol[Bb * Nn * Cc];

// ---------------------------- PTX helpers ----------------------------------
#define LDSM4(r0, r1, r2, r3, addr)                                          \
    asm volatile("ldmatrix.sync.aligned.m8n8.x4.shared.b16 {%0,%1,%2,%3},[%4];" \
                 : "=r"(r0), "=r"(r1), "=r"(r2), "=r"(r3) : "r"(addr))
#define LDSM4T(r0, r1, r2, r3, addr)                                         \
    asm volatile("ldmatrix.sync.aligned.m8n8.x4.trans.shared.b16 {%0,%1,%2,%3},[%4];" \
                 : "=r"(r0), "=r"(r1), "=r"(r2), "=r"(r3) : "r"(addr))
#define MMA16816(c, a, b)                                                    \
    asm volatile("mma.sync.aligned.m16n8k16.row.col.f32.bf16.bf16.f32 "      \
                 "{%0,%1,%2,%3},{%4,%5,%6,%7},{%8,%9},{%0,%1,%2,%3};"        \
                 : "+f"((c)[0]), "+f"((c)[1]), "+f"((c)[2]), "+f"((c)[3])    \
                 : "r"((a)[0]), "r"((a)[1]), "r"((a)[2]), "r"((a)[3]),       \
                   "r"((b)[0]), "r"((b)[1]))
#define CP_ASYNC16(dst, src)                                                 \
    asm volatile("cp.async.cg.shared.global [%0],[%1],16;" :: "r"(dst), "l"(src))
#define CP_COMMIT() asm volatile("cp.async.commit_group;")
#define CP_WAIT2()  asm volatile("cp.async.wait_group 2;")
#define CP_WAIT1()  asm volatile("cp.async.wait_group 1;")
#define CP_WAIT0()  asm volatile("cp.async.wait_group 0;")

__device__ __forceinline__ uint32_t packbf(float lo, float hi) {
    uint32_t r;
    asm("cvt.rn.bf16x2.f32 %0,%1,%2;" : "=r"(r) : "f"(hi), "f"(lo));
    return r;
}
__device__ __forceinline__ void split2(float v0, float v1,
                                       uint32_t& hi, uint32_t& lo) {
    __nv_bfloat16 h0 = __float2bfloat16(v0), h1 = __float2bfloat16(v1);
    hi = ((uint32_t)__bfloat16_as_ushort(h1) << 16) | __bfloat16_as_ushort(h0);
    lo = packbf(v0 - __bfloat162float(h0), v1 - __bfloat162float(h1));
}

// ------------------------- fp32 -> bf16 hi/lo split -------------------------
__global__ __launch_bounds__(256) void cvt_kernel(const float4* __restrict__ in,
                                                  int which, int n4)
{
    int i = blockIdx.x * 256 + threadIdx.x;
    if (i >= n4) return;
    __nv_bfloat16 *hi, *lo;
    if (which == 0)      { hi = g_xh;  lo = g_xl;  }
    else if (which == 1) { hi = g_wih; lo = g_wil; }
    else                 { hi = g_woh; lo = g_wol; }
    float4 f = in[i];
    uint32_t h01, l01, h23, l23;
    split2(f.x, f.y, h01, l01);
    split2(f.z, f.w, h23, l23);
    ((uint2*)hi)[i] = make_uint2(h01, h23);
    ((uint2*)lo)[i] = make_uint2(l01, l23);
}

// ---------------------------------------------------------------------------
// bf16x3 TN GEMM (legacy HMMA): C[m,n] = sum_k A[m,k]*W[n,k] + bias[n]
// CTA tile 128x256, BK=32, 3-stage cp.async, 8 warps, warp tile 64x64.
// acc += Ah*Wh + Ah*Wl + Al*Wh (fp32 MMA accumulators).
// EPI=0: A=x(hi/lo), W=w_in(hi/lo); scatter q/k/v bf16 hi/lo (q scaled).
// EPI=1: A=attn-out(hi/lo), W=w_out(hi/lo); fp32 out.
// ---------------------------------------------------------------------------
#define LDS 40                       // padded bf16 row stride (80 B)
#define AMATG (128 * LDS * 2)        // 10240 B
#define BMATG (256 * LDS * 2)        // 20480 B
#define GSTG (2 * AMATG + 2 * BMATG) // 61440 B / stage
#define GSMEM (3 * GSTG)             // 184320 B

template <int EPI>
__device__ __forceinline__ void tg_load(uint32_t sbase, int bm, int bn,
                                        int k0, int tid)
{
    const __nv_bfloat16* Ah = (EPI == 0) ? g_xh : g_aoh;
    const __nv_bfloat16* Al = (EPI == 0) ? g_xl : g_aol;
    const __nv_bfloat16* Wh = (EPI == 0) ? g_wih : g_woh;
    const __nv_bfloat16* Wl = (EPI == 0) ? g_wil : g_wol;
#pragma unroll
    for (int u = 0; u < 2; u++) {              // A: 128 rows x 4 x 16B
        int idx = u * 256 + tid;
        int row = idx >> 2, q = idx & 3;
        uint32_t soff = (uint32_t)(row * LDS + q * 8) * 2;
        size_t ga = (size_t)(bm + row) * 1024 + k0 + q * 8;
        CP_ASYNC16(sbase + soff, Ah + ga);
        CP_ASYNC16(sbase + AMATG + soff, Al + ga);
    }
#pragma unroll
    for (int u = 0; u < 4; u++) {              // B: 256 rows x 4 x 16B
        int idx = u * 256 + tid;
        int row = idx >> 2, q = idx & 3;
        uint32_t soff = (uint32_t)(row * LDS + q * 8) * 2;
        size_t gw = (size_t)(bn + row) * 1024 + k0 + q * 8;
        CP_ASYNC16(sbase + 2 * AMATG + soff, Wh + gw);
        CP_ASYNC16(sbase + 2 * AMATG + BMATG + soff, Wl + gw);
    }
}

template <int EPI>
__global__ __launch_bounds__(256, 1) void gemm_mma(const float* __restrict__ bias,
                                                   float* __restrict__ out)
{
    extern __shared__ __align__(16) char smem[];
    const uint32_t sm0 = (uint32_t)__cvta_generic_to_shared(smem);

    const int tid  = threadIdx.x;
    const int lane = tid & 31;
    const int wid  = tid >> 5;
    const int wm = (wid & 1) * 64;     // warp m offset
    const int wn = (wid >> 1) * 64;    // warp n offset
    const int bm = blockIdx.y * 128;
    const int bn = blockIdx.x * 256;

    // A x4-ldmatrix lane offset (m16k16 fragment)
    const int lr = lane & 7, lq = lane >> 3;
    const uint32_t a_off =
        (uint32_t)(((wm + (lq & 1) * 8 + lr) * LDS + (lq >> 1) * 8) * 2);
    // B x4-ldmatrix lane offset (n16k16: frags {r0,r1}=n0-7, {r2,r3}=n8-15)
    const uint32_t b_off =
        (uint32_t)(((wn + (lane & 7) + ((lane >> 4) & 1) * 8) * LDS
                    + ((lane >> 3) & 1) * 8) * 2);

    float c[4][8][4];
#pragma unroll
    for (int im = 0; im < 4; im++)
#pragma unroll
        for (int jn = 0; jn < 8; jn++)
#pragma unroll
            for (int q = 0; q < 4; q++) c[im][jn][q] = 0.0f;

    tg_load<EPI>(sm0 + 0 * GSTG, bm, bn, 0, tid);
    CP_COMMIT();
    tg_load<EPI>(sm0 + 1 * GSTG, bm, bn, 32, tid);
    CP_COMMIT();

    for (int ch = 0; ch < 32; ch++) {
        if (ch < 30) {
            tg_load<EPI>(sm0 + ((ch + 2) % 3) * GSTG, bm, bn, (ch + 2) * 32, tid);
            CP_COMMIT();
            CP_WAIT2();
        } else if (ch == 30) {
            CP_WAIT1();
        } else {
            CP_WAIT0();
        }
        __syncthreads();

        const uint32_t st = sm0 + (ch % 3) * GSTG;
        const uint32_t tAh = st, tAl = st + AMATG;
        const uint32_t tBh = st + 2 * AMATG, tBl = st + 2 * AMATG + BMATG;

#pragma unroll
        for (int ks = 0; ks < 2; ks++) {
            uint32_t aH[4][4], aL[4][4];
#pragma unroll
            for (int im = 0; im < 4; im++) {
                uint32_t off = a_off + (uint32_t)(im * 16 * LDS * 2 + ks * 32);
                LDSM4(aH[im][0], aH[im][1], aH[im][2], aH[im][3], tAh + off);
                LDSM4(aL[im][0], aL[im][1], aL[im][2], aL[im][3], tAl + off);
            }
#pragma unroll
            for (int jn2 = 0; jn2 < 4; jn2++) {
                uint32_t bh[4], bl[4];
                uint32_t off = b_off + (uint32_t)(jn2 * 16 * LDS * 2 + ks * 32);
                LDSM4(bh[0], bh[1], bh[2], bh[3], tBh + off);
                LDSM4(bl[0], bl[1], bl[2], bl[3], tBl + off);
#pragma unroll
                for (int im = 0; im < 4; im++) {
                    MMA16816(c[im][2 * jn2],     aH[im], &bh[0]);
                    MMA16816(c[im][2 * jn2],     aH[im], &bl[0]);
                    MMA16816(c[im][2 * jn2],     aL[im], &bh[0]);
                    MMA16816(c[im][2 * jn2 + 1], aH[im], &bh[2]);
                    MMA16816(c[im][2 * jn2 + 1], aH[im], &bl[2]);
                    MMA16816(c[im][2 * jn2 + 1], aL[im], &bh[2]);
                }
            }
        }
        __syncthreads();
    }

    // epilogue
#pragma unroll
    for (int im = 0; im < 4; im++) {
#pragma unroll
        for (int jn = 0; jn < 8; jn++) {
            int r0 = bm + wm + im * 16 + (lane >> 2);
            int cg = bn + wn + jn * 8 + 2 * (lane & 3);
            float b0 = bias[cg], b1 = bias[cg + 1];
#pragma unroll
            for (int half = 0; half < 2; half++) {
                int r = r0 + half * 8;
                float v0 = c[im][jn][half * 2 + 0] + b0;
                float v1 = c[im][jn][half * 2 + 1] + b1;
                if (EPI == 0) {
                    int b = r >> 10, nn = r & 1023;
                    int s = cg >> 10;
                    int h = (cg >> 6) & 15;
                    int d = cg & 63;
                    if (s == 0) { v0 *= 0.125f; v1 *= 0.125f; }  // fold QK scale
                    __nv_bfloat16 *hiA = (s == 0) ? g_qh : (s == 1) ? g_kh : g_vh;
                    __nv_bfloat16 *loA = (s == 0) ? g_ql : (s == 1) ? g_kl : g_vl;
                    size_t idx = (((size_t)b * Hh + h) * Nn + nn) * Dd + d;
                    uint32_t hp, lp;
                    split2(v0, v1, hp, lp);
                    *(uint32_t*)&hiA[idx] = hp;
                    *(uint32_t*)&loA[idx] = lp;
                } else {
                    *(float2*)&out[(size_t)r * 1024 + cg] = make_float2(v0, v1);
                }
            }
        }
    }
}

// ---------------------------------------------------------------------------
// MMA flash attention (unchanged from R6, ~290us).
// ---------------------------------------------------------------------------
#define ASTG 36864
#define AMAT 9216

__global__ __launch_bounds__(256, 1) void attn_mma()
{
    extern __shared__ __align__(16) char smem[];
    const uint32_t sm0 = (uint32_t)__cvta_generic_to_shared(smem);

    const int tid  = threadIdx.x;
    const int lane = tid & 31;
    const int wq   = tid >> 5;
    const int bh = blockIdx.y;
    const int q0 = blockIdx.x * 128;

    const __nv_bfloat16* Qhp = g_qh + (size_t)bh * NDh;
    const __nv_bfloat16* Qlp = g_ql + (size_t)bh * NDh;
    const __nv_bfloat16* Khp = g_kh + (size_t)bh * NDh;
    const __nv_bfloat16* Klp = g_kl + (size_t)bh * NDh;
    const __nv_bfloat16* Vhp = g_vh + (size_t)bh * NDh;
    const __nv_bfloat16* Vlp = g_vl + (size_t)bh * NDh;

    const uint32_t qbase = sm0 + ASTG;
#pragma unroll
    for (int u = 0; u < 8; u++) {
        const __nv_bfloat16* mp = (u < 4) ? Qhp : Qlp;
        int r = (u & 3) * 32 + (tid >> 3);
        int cc = tid & 7;
        CP_ASYNC16(qbase + (u >> 2) * (128 * 144) + r * 144 + cc * 16,
                   mp + (size_t)(q0 + r) * 64 + cc * 8);
    }
    CP_COMMIT();
    {
#pragma unroll
        for (int u = 0; u < 8; u++) {
            const __nv_bfloat16* mp = (u < 2) ? Khp : (u < 4) ? Klp
                                     : (u < 6) ? Vhp : Vlp;
            int r = (u & 1) * 32 + (tid >> 3);
            int cc = tid & 7;
            CP_ASYNC16(sm0 + (u >> 1) * AMAT + r * 144 + cc * 16,
                       mp + (size_t)r * 64 + cc * 8);
        }
        CP_COMMIT();
    }
    CP_WAIT1();
    __syncthreads();

    uint32_t qfh[4][4], qfl[4][4];
    {
        const int lr = lane & 7, lq = lane >> 3;
        uint32_t qa = qbase + (uint32_t)((wq * 16 + (lq & 1) * 8 + lr) * 144
                                         + (lq >> 1) * 16);
#pragma unroll
        for (int ks = 0; ks < 4; ks++) {
            LDSM4(qfh[ks][0], qfh[ks][1], qfh[ks][2], qfh[ks][3], qa + ks * 32);
            LDSM4(qfl[ks][0], qfl[ks][1], qfl[ks][2], qfl[ks][3],
                  qa + 128 * 144 + ks * 32);
        }
    }
    __syncthreads();

    float o[8][4];
    float mrow[2] = {-1e30f, -1e30f}, lrow[2] = {0.0f, 0.0f};
#pragma unroll
    for (int j = 0; j < 8; j++)
#pragma unroll
        for (int q = 0; q < 4; q++) o[j][q] = 0.0f;

    for (int t = 0; t < 16; t++) {
        if (t < 15) {
            uint32_t nb = sm0 + ((t + 1) & 1) * ASTG;
            int key0 = (t + 1) * 64;
#pragma unroll
            for (int u = 0; u < 8; u++) {
                const __nv_bfloat16* mp = (u < 2) ? Khp : (u < 4) ? Klp
                                         : (u < 6) ? Vhp : Vlp;
                int r = (u & 1) * 32 + (tid >> 3);
                int cc = tid & 7;
                CP_ASYNC16(nb + (u >> 1) * AMAT + r * 144 + cc * 16,
                           mp + (size_t)(key0 + r) * 64 + cc * 8);
            }
            CP_COMMIT();
            CP_WAIT1();
        } else {
            CP_WAIT0();
        }
        __syncthreads();

        const uint32_t st = sm0 + (t & 1) * ASTG;

        float s[8][4];
#pragma unroll
        for (int j = 0; j < 8; j++)
#pragma unroll
            for (int q = 0; q < 4; q++) s[j][q] = 0.0f;

        const uint32_t kaddr = st + (uint32_t)(((lane & 7) + ((lane >> 4) & 1) * 8) * 144
                                               + ((lane >> 3) & 1) * 16);
#pragma unroll
        for (int ks = 0; ks < 4; ks++) {
            uint32_t kh[4][4], kl[4][4];
#pragma unroll
            for (int jn2 = 0; jn2 < 4; jn2++) {
                uint32_t off = kaddr + (uint32_t)(jn2 * 16 * 144 + ks * 32);
                LDSM4(kh[jn2][0], kh[jn2][1], kh[jn2][2], kh[jn2][3], off);
                LDSM4(kl[jn2][0], kl[jn2][1], kl[jn2][2], kl[jn2][3], off + AMAT);
            }
#pragma unroll
            for (int jn2 = 0; jn2 < 4; jn2++) {
                MMA16816(s[2 * jn2],     qfh[ks], &kh[jn2][0]);
                MMA16816(s[2 * jn2],     qfh[ks], &kl[jn2][0]);
                MMA16816(s[2 * jn2],     qfl[ks], &kh[jn2][0]);
                MMA16816(s[2 * jn2 + 1], qfh[ks], &kh[jn2][2]);
                MMA16816(s[2 * jn2 + 1], qfh[ks], &kl[jn2][2]);
                MMA16816(s[2 * jn2 + 1], qfl[ks], &kh[jn2][2]);
            }
        }

#pragma unroll
        for (int r = 0; r < 2; r++) {
            float mx = -1e30f;
#pragma unroll
            for (int j = 0; j < 8; j++)
                mx = fmaxf(mx, fmaxf(s[j][2 * r], s[j][2 * r + 1]));
            mx = fmaxf(mx, __shfl_xor_sync(0xffffffffu, mx, 1));
            mx = fmaxf(mx, __shfl_xor_sync(0xffffffffu, mx, 2));
            float mnew = fmaxf(mrow[r], mx);
            float corr = __expf(mrow[r] - mnew);
            float sum = 0.0f;
#pragma unroll
            for (int j = 0; j < 8; j++) {
                s[j][2 * r]     = __expf(s[j][2 * r]     - mnew);
                s[j][2 * r + 1] = __expf(s[j][2 * r + 1] - mnew);
                sum += s[j][2 * r] + s[j][2 * r + 1];
            }
            sum += __shfl_xor_sync(0xffffffffu, sum, 1);
            sum += __shfl_xor_sync(0xffffffffu, sum, 2);
            lrow[r] = lrow[r] * corr + sum;
            mrow[r] = mnew;
#pragma unroll
            for (int j = 0; j < 8; j++) {
                o[j][2 * r]     *= corr;
                o[j][2 * r + 1] *= corr;
            }
        }

        const uint32_t vaddr = st + 2 * AMAT
            + (uint32_t)((lane & 15) * 144 + (lane >> 4) * 16);
#pragma unroll
        for (int ks2 = 0; ks2 < 4; ks2++) {
            uint32_t pah[4], pal[4];
            float* s0 = s[2 * ks2];
            float* s1 = s[2 * ks2 + 1];
            split2(s0[0], s0[1], pah[0], pal[0]);
            split2(s0[2], s0[3], pah[1], pal[1]);
            split2(s1[0], s1[1], pah[2], pal[2]);
            split2(s1[2], s1[3], pah[3], pal[3]);

            uint32_t vrow = vaddr + (uint32_t)(ks2 * 16 * 144);
#pragma unroll
            for (int jd2 = 0; jd2 < 4; jd2++) {
                uint32_t vh[4], vl[4];
                uint32_t off = vrow + (uint32_t)(jd2 * 32);
                LDSM4T(vh[0], vh[1], vh[2], vh[3], off);
                LDSM4T(vl[0], vl[1], vl[2], vl[3], off + AMAT);
                MMA16816(o[2 * jd2],     pah, &vh[0]);
                MMA16816(o[2 * jd2],     pah, &vl[0]);
                MMA16816(o[2 * jd2],     pal, &vh[0]);
                MMA16816(o[2 * jd2 + 1], pah, &vh[2]);
                MMA16816(o[2 * jd2 + 1], pah, &vl[2]);
                MMA16816(o[2 * jd2 + 1], pal, &vh[2]);
            }
        }
        __syncthreads();
    }

    const int b = bh >> 4, h = bh & 15;
    const int G = lane >> 2, T = lane & 3;
#pragma unroll
    for (int r = 0; r < 2; r++) {
        float inv = 1.0f / lrow[r];
        int row = q0 + wq * 16 + G + r * 8;
        size_t base = ((size_t)b * Nn + row) * Cc + h * 64;
#pragma unroll
        for (int jd = 0; jd < 8; jd++) {
            float v0 = o[jd][2 * r] * inv;
            float v1 = o[jd][2 * r + 1] * inv;
            int col = jd * 8 + 2 * T;
            uint32_t hp, lp;
            split2(v0, v1, hp, lp);
            *(uint32_t*)&g_aoh[base + col] = hp;
            *(uint32_t*)&g_aol[base + col] = lp;
        }
    }
}

// ---------------------------------------------------------------------------
extern "C" void kernel_launch(void* const* d_in, const int* in_sizes, int n_in,
                              void* d_out, int out_size)
{
    const float* x     = (const float*)d_in[0];
    const float* w_in  = (const float*)d_in[1];
    const float* b_in  = (const float*)d_in[2];
    const float* w_out = (const float*)d_in[3];
    const float* b_out = (const float*)d_in[4];
    float* out = (float*)d_out;

    cudaFuncSetAttribute(gemm_mma<0>,
                         cudaFuncAttributeMaxDynamicSharedMemorySize, GSMEM);
    cudaFuncSetAttribute(gemm_mma<1>,
                         cudaFuncAttributeMaxDynamicSharedMemorySize, GSMEM);
    cudaFuncSetAttribute(attn_mma,
                         cudaFuncAttributeMaxDynamicSharedMemorySize, 2 * ASTG);

    cvt_kernel<<<(Bb * Nn * Cc / 4 + 255) / 256, 256>>>((const float4*)x, 0, Bb * Nn * Cc / 4);
    cvt_kernel<<<(3 * Cc * Cc / 4 + 255) / 256, 256>>>((const float4*)w_in, 1, 3 * Cc * Cc / 4);
    cvt_kernel<<<(Cc * Cc / 4 + 255) / 256, 256>>>((const float4*)w_out, 2, Cc * Cc / 4);

    // QKV projection: 8192 x 3072 x 1024 -> q/k/v bf16 hi/lo (q pre-scaled)
    gemm_mma<0><<<dim3(12, 64), 256, GSMEM>>>(b_in, nullptr);
    // Attention: 8 q-tiles x 128 (b,h)
    attn_mma<<<dim3(8, 128), 256, 2 * ASTG>>>();
    // Output projection: 8192 x 1024 x 1024
    gemm_mma<1><<<dim3(4, 64), 256, GSMEM>>>(b_out, out);
}

// round 9
// speedup vs baseline: 2.9628x; 1.0788x over previous
#include <cuda_runtime.h>
#include <cuda_bf16.h>
#include <cstdint>

#define Bb 8
#define Nn 1024
#define Cc 1024
#define Hh 16
#define Dd 64
#define NDh (Nn * Dd)

// ---------------- scratch (device globals; allocation-free) ----------------
__device__ __align__(16) __nv_bfloat16 g_xh[Bb * Nn * Cc], g_xl[Bb * Nn * Cc];
__device__ __align__(16) __nv_bfloat16 g_wih[3 * Cc * Cc], g_wil[3 * Cc * Cc];
__device__ __align__(16) __nv_bfloat16 g_woh[Cc * Cc], g_wol[Cc * Cc];
__device__ __align__(16) __nv_bfloat16 g_qh[Bb * Hh * NDh], g_ql[Bb * Hh * NDh];
__device__ __align__(16) __nv_bfloat16 g_kh[Bb * Hh * NDh], g_kl[Bb * Hh * NDh];
__device__ __align__(16) __nv_bfloat16 g_vh[Bb * Hh * NDh], g_vl[Bb * Hh * NDh];
__device__ __align__(16) __nv_bfloat16 g_aoh[Bb * Nn * Cc], g_aol[Bb * Nn * Cc];

// ---------------------------- PTX helpers ----------------------------------
#define LDSM4(r0, r1, r2, r3, addr)                                          \
    asm volatile("ldmatrix.sync.aligned.m8n8.x4.shared.b16 {%0,%1,%2,%3},[%4];" \
                 : "=r"(r0), "=r"(r1), "=r"(r2), "=r"(r3) : "r"(addr))
#define LDSM4T(r0, r1, r2, r3, addr)                                         \
    asm volatile("ldmatrix.sync.aligned.m8n8.x4.trans.shared.b16 {%0,%1,%2,%3},[%4];" \
                 : "=r"(r0), "=r"(r1), "=r"(r2), "=r"(r3) : "r"(addr))
#define MMA16816(c, a, b)                                                    \
    asm volatile("mma.sync.aligned.m16n8k16.row.col.f32.bf16.bf16.f32 "      \
                 "{%0,%1,%2,%3},{%4,%5,%6,%7},{%8,%9},{%0,%1,%2,%3};"        \
                 : "+f"((c)[0]), "+f"((c)[1]), "+f"((c)[2]), "+f"((c)[3])    \
                 : "r"((a)[0]), "r"((a)[1]), "r"((a)[2]), "r"((a)[3]),       \
                   "r"((b)[0]), "r"((b)[1]))
#define CP_ASYNC16(dst, src)                                                 \
    asm volatile("cp.async.cg.shared.global [%0],[%1],16;" :: "r"(dst), "l"(src))
#define CP_COMMIT() asm volatile("cp.async.commit_group;")
#define CP_WAIT1()  asm volatile("cp.async.wait_group 1;")
#define CP_WAIT0()  asm volatile("cp.async.wait_group 0;")

__device__ __forceinline__ uint32_t packbf(float lo, float hi) {
    uint32_t r;
    asm("cvt.rn.bf16x2.f32 %0,%1,%2;" : "=r"(r) : "f"(hi), "f"(lo));
    return r;
}
__device__ __forceinline__ void split2(float v0, float v1,
                                       uint32_t& hi, uint32_t& lo) {
    __nv_bfloat16 h0 = __float2bfloat16(v0), h1 = __float2bfloat16(v1);
    hi = ((uint32_t)__bfloat16_as_ushort(h1) << 16) | __bfloat16_as_ushort(h0);
    lo = packbf(v0 - __bfloat162float(h0), v1 - __bfloat162float(h1));
}

// ------------------------- fp32 -> bf16 hi/lo split -------------------------
__global__ __launch_bounds__(256) void cvt_kernel(const float4* __restrict__ in,
                                                  int which, int n4)
{
    int i = blockIdx.x * 256 + threadIdx.x;
    if (i >= n4) return;
    __nv_bfloat16 *hi, *lo;
    if (which == 0)      { hi = g_xh;  lo = g_xl;  }
    else if (which == 1) { hi = g_wih; lo = g_wil; }
    else                 { hi = g_woh; lo = g_wol; }
    float4 f = in[i];
    uint32_t h01, l01, h23, l23;
    split2(f.x, f.y, h01, l01);
    split2(f.z, f.w, h23, l23);
    ((uint2*)hi)[i] = make_uint2(h01, h23);
    ((uint2*)lo)[i] = make_uint2(l01, l23);
}

// ---------------------------------------------------------------------------
// bf16x3 TN GEMM (HMMA): C[m,n] = sum_k A[m,k]*W[n,k] + bias[n]
// CTA tile 128x128, BK=32, 2-stage cp.async, 8 warps (4m x 2n),
// warp tile 32x64. __launch_bounds__(256,2) -> 2 CTAs/SM (occupancy fix).
// acc += Ah*Wh + Ah*Wl + Al*Wh (fp32 MMA accumulators).
// EPI=0: A=x(hi/lo), W=w_in(hi/lo); scatter q/k/v bf16 hi/lo (q scaled).
// EPI=1: A=attn-out(hi/lo), W=w_out(hi/lo); fp32 out.
// ---------------------------------------------------------------------------
#define LDS 40                       // padded bf16 row stride (80 B)
#define MATG (128 * LDS * 2)         // 10240 B per matrix
#define GSTG (4 * MATG)              // 40960 B / stage
#define GSMEM (2 * GSTG)             // 81920 B

template <int EPI>
__device__ __forceinline__ void tg_load(uint32_t sbase, int bm, int bn,
                                        int k0, int tid)
{
    const __nv_bfloat16* Ah = (EPI == 0) ? g_xh : g_aoh;
    const __nv_bfloat16* Al = (EPI == 0) ? g_xl : g_aol;
    const __nv_bfloat16* Wh = (EPI == 0) ? g_wih : g_woh;
    const __nv_bfloat16* Wl = (EPI == 0) ? g_wil : g_wol;
#pragma unroll
    for (int u = 0; u < 2; u++) {
        int idx = u * 256 + tid;          // 0..511
        int row = idx >> 2, q = idx & 3;
        uint32_t soff = (uint32_t)(row * LDS + q * 8) * 2;
        size_t ga = (size_t)(bm + row) * 1024 + k0 + q * 8;
        size_t gw = (size_t)(bn + row) * 1024 + k0 + q * 8;
        CP_ASYNC16(sbase + 0 * MATG + soff, Ah + ga);
        CP_ASYNC16(sbase + 1 * MATG + soff, Al + ga);
        CP_ASYNC16(sbase + 2 * MATG + soff, Wh + gw);
        CP_ASYNC16(sbase + 3 * MATG + soff, Wl + gw);
    }
}

template <int EPI>
__global__ __launch_bounds__(256, 2) void gemm_mma(const float* __restrict__ bias,
                                                   float* __restrict__ out)
{
    extern __shared__ __align__(16) char smem[];
    const uint32_t sm0 = (uint32_t)__cvta_generic_to_shared(smem);

    const int tid  = threadIdx.x;
    const int lane = tid & 31;
    const int wid  = tid >> 5;
    const int wm = (wid & 3) * 32;     // warp m offset (4 groups)
    const int wn = (wid >> 2) * 64;    // warp n offset (2 groups)
    const int bm = blockIdx.y * 128;
    const int bn = blockIdx.x * 128;

    // A x4-ldmatrix lane offset (m16k16)
    const int lr = lane & 7, lq = lane >> 3;
    const uint32_t a_off =
        (uint32_t)(((wm + (lq & 1) * 8 + lr) * LDS + (lq >> 1) * 8) * 2);
    // B x4-ldmatrix lane offset (n16k16: {r0,r1}=n0-7, {r2,r3}=n8-15)
    const uint32_t b_off =
        (uint32_t)(((wn + (lane & 7) + ((lane >> 4) & 1) * 8) * LDS
                    + ((lane >> 3) & 1) * 8) * 2);

    float c[2][8][4];
#pragma unroll
    for (int im = 0; im < 2; im++)
#pragma unroll
        for (int jn = 0; jn < 8; jn++)
#pragma unroll
            for (int q = 0; q < 4; q++) c[im][jn][q] = 0.0f;

    tg_load<EPI>(sm0 + 0 * GSTG, bm, bn, 0, tid);
    CP_COMMIT();

    for (int ch = 0; ch < 32; ch++) {
        if (ch < 31) {
            tg_load<EPI>(sm0 + ((ch + 1) & 1) * GSTG, bm, bn, (ch + 1) * 32, tid);
            CP_COMMIT();
            CP_WAIT1();
        } else {
            CP_WAIT0();
        }
        __syncthreads();

        const uint32_t st = sm0 + (ch & 1) * GSTG;
        const uint32_t tAh = st, tAl = st + MATG;
        const uint32_t tBh = st + 2 * MATG, tBl = st + 3 * MATG;

#pragma unroll
        for (int ks = 0; ks < 2; ks++) {
            uint32_t aH[2][4], aL[2][4];
#pragma unroll
            for (int im = 0; im < 2; im++) {
                uint32_t off = a_off + (uint32_t)(im * 16 * LDS * 2 + ks * 32);
                LDSM4(aH[im][0], aH[im][1], aH[im][2], aH[im][3], tAh + off);
                LDSM4(aL[im][0], aL[im][1], aL[im][2], aL[im][3], tAl + off);
            }
#pragma unroll
            for (int jn2 = 0; jn2 < 4; jn2++) {
                uint32_t bh[4], bl[4];
                uint32_t off = b_off + (uint32_t)(jn2 * 16 * LDS * 2 + ks * 32);
                LDSM4(bh[0], bh[1], bh[2], bh[3], tBh + off);
                LDSM4(bl[0], bl[1], bl[2], bl[3], tBl + off);
                // interleave across 4 independent accumulators (dep dist 4)
#pragma unroll
                for (int im = 0; im < 2; im++) {
                    MMA16816(c[im][2 * jn2],     aH[im], &bh[0]);
                    MMA16816(c[im][2 * jn2 + 1], aH[im], &bh[2]);
                }
#pragma unroll
                for (int im = 0; im < 2; im++) {
                    MMA16816(c[im][2 * jn2],     aH[im], &bl[0]);
                    MMA16816(c[im][2 * jn2 + 1], aH[im], &bl[2]);
                }
#pragma unroll
                for (int im = 0; im < 2; im++) {
                    MMA16816(c[im][2 * jn2],     aL[im], &bh[0]);
                    MMA16816(c[im][2 * jn2 + 1], aL[im], &bh[2]);
                }
            }
        }
        __syncthreads();
    }

    // epilogue
#pragma unroll
    for (int im = 0; im < 2; im++) {
#pragma unroll
        for (int jn = 0; jn < 8; jn++) {
            int r0 = bm + wm + im * 16 + (lane >> 2);
            int cg = bn + wn + jn * 8 + 2 * (lane & 3);
            float b0 = bias[cg], b1 = bias[cg + 1];
#pragma unroll
            for (int half = 0; half < 2; half++) {
                int r = r0 + half * 8;
                float v0 = c[im][jn][half * 2 + 0] + b0;
                float v1 = c[im][jn][half * 2 + 1] + b1;
                if (EPI == 0) {
                    int b = r >> 10, nn = r & 1023;
                    int s = cg >> 10;
                    int h = (cg >> 6) & 15;
                    int d = cg & 63;
                    if (s == 0) { v0 *= 0.125f; v1 *= 0.125f; }  // fold QK scale
                    __nv_bfloat16 *hiA = (s == 0) ? g_qh : (s == 1) ? g_kh : g_vh;
                    __nv_bfloat16 *loA = (s == 0) ? g_ql : (s == 1) ? g_kl : g_vl;
                    size_t idx = (((size_t)b * Hh + h) * Nn + nn) * Dd + d;
                    uint32_t hp, lp;
                    split2(v0, v1, hp, lp);
                    *(uint32_t*)&hiA[idx] = hp;
                    *(uint32_t*)&loA[idx] = lp;
                } else {
                    *(float2*)&out[(size_t)r * 1024 + cg] = make_float2(v0, v1);
                }
            }
        }
    }
}

// ---------------------------------------------------------------------------
// MMA flash attention (unchanged from R6, ~290us).
// ---------------------------------------------------------------------------
#define ASTG 36864
#define AMAT 9216

__global__ __launch_bounds__(256, 1) void attn_mma()
{
    extern __shared__ __align__(16) char smem[];
    const uint32_t sm0 = (uint32_t)__cvta_generic_to_shared(smem);

    const int tid  = threadIdx.x;
    const int lane = tid & 31;
    const int wq   = tid >> 5;
    const int bh = blockIdx.y;
    const int q0 = blockIdx.x * 128;

    const __nv_bfloat16* Qhp = g_qh + (size_t)bh * NDh;
    const __nv_bfloat16* Qlp = g_ql + (size_t)bh * NDh;
    const __nv_bfloat16* Khp = g_kh + (size_t)bh * NDh;
    const __nv_bfloat16* Klp = g_kl + (size_t)bh * NDh;
    const __nv_bfloat16* Vhp = g_vh + (size_t)bh * NDh;
    const __nv_bfloat16* Vlp = g_vl + (size_t)bh * NDh;

    const uint32_t qbase = sm0 + ASTG;
#pragma unroll
    for (int u = 0; u < 8; u++) {
        const __nv_bfloat16* mp = (u < 4) ? Qhp : Qlp;
        int r = (u & 3) * 32 + (tid >> 3);
        int cc = tid & 7;
        CP_ASYNC16(qbase + (u >> 2) * (128 * 144) + r * 144 + cc * 16,
                   mp + (size_t)(q0 + r) * 64 + cc * 8);
    }
    CP_COMMIT();
    {
#pragma unroll
        for (int u = 0; u < 8; u++) {
            const __nv_bfloat16* mp = (u < 2) ? Khp : (u < 4) ? Klp
                                     : (u < 6) ? Vhp : Vlp;
            int r = (u & 1) * 32 + (tid >> 3);
            int cc = tid & 7;
            CP_ASYNC16(sm0 + (u >> 1) * AMAT + r * 144 + cc * 16,
                       mp + (size_t)r * 64 + cc * 8);
        }
        CP_COMMIT();
    }
    CP_WAIT1();
    __syncthreads();

    uint32_t qfh[4][4], qfl[4][4];
    {
        const int lr = lane & 7, lq = lane >> 3;
        uint32_t qa = qbase + (uint32_t)((wq * 16 + (lq & 1) * 8 + lr) * 144
                                         + (lq >> 1) * 16);
#pragma unroll
        for (int ks = 0; ks < 4; ks++) {
            LDSM4(qfh[ks][0], qfh[ks][1], qfh[ks][2], qfh[ks][3], qa + ks * 32);
            LDSM4(qfl[ks][0], qfl[ks][1], qfl[ks][2], qfl[ks][3],
                  qa + 128 * 144 + ks * 32);
        }
    }
    __syncthreads();

    float o[8][4];
    float mrow[2] = {-1e30f, -1e30f}, lrow[2] = {0.0f, 0.0f};
#pragma unroll
    for (int j = 0; j < 8; j++)
#pragma unroll
        for (int q = 0; q < 4; q++) o[j][q] = 0.0f;

    for (int t = 0; t < 16; t++) {
        if (t < 15) {
            uint32_t nb = sm0 + ((t + 1) & 1) * ASTG;
            int key0 = (t + 1) * 64;
#pragma unroll
            for (int u = 0; u < 8; u++) {
                const __nv_bfloat16* mp = (u < 2) ? Khp : (u < 4) ? Klp
                                         : (u < 6) ? Vhp : Vlp;
                int r = (u & 1) * 32 + (tid >> 3);
                int cc = tid & 7;
                CP_ASYNC16(nb + (u >> 1) * AMAT + r * 144 + cc * 16,
                           mp + (size_t)(key0 + r) * 64 + cc * 8);
            }
            CP_COMMIT();
            CP_WAIT1();
        } else {
            CP_WAIT0();
        }
        __syncthreads();

        const uint32_t st = sm0 + (t & 1) * ASTG;

        float s[8][4];
#pragma unroll
        for (int j = 0; j < 8; j++)
#pragma unroll
            for (int q = 0; q < 4; q++) s[j][q] = 0.0f;

        const uint32_t kaddr = st + (uint32_t)(((lane & 7) + ((lane >> 4) & 1) * 8) * 144
                                               + ((lane >> 3) & 1) * 16);
#pragma unroll
        for (int ks = 0; ks < 4; ks++) {
            uint32_t kh[4][4], kl[4][4];
#pragma unroll
            for (int jn2 = 0; jn2 < 4; jn2++) {
                uint32_t off = kaddr + (uint32_t)(jn2 * 16 * 144 + ks * 32);
                LDSM4(kh[jn2][0], kh[jn2][1], kh[jn2][2], kh[jn2][3], off);
                LDSM4(kl[jn2][0], kl[jn2][1], kl[jn2][2], kl[jn2][3], off + AMAT);
            }
#pragma unroll
            for (int jn2 = 0; jn2 < 4; jn2++) {
                MMA16816(s[2 * jn2],     qfh[ks], &kh[jn2][0]);
                MMA16816(s[2 * jn2],     qfh[ks], &kl[jn2][0]);
                MMA16816(s[2 * jn2],     qfl[ks], &kh[jn2][0]);
                MMA16816(s[2 * jn2 + 1], qfh[ks], &kh[jn2][2]);
                MMA16816(s[2 * jn2 + 1], qfh[ks], &kl[jn2][2]);
                MMA16816(s[2 * jn2 + 1], qfl[ks], &kh[jn2][2]);
            }
        }

#pragma unroll
        for (int r = 0; r < 2; r++) {
            float mx = -1e30f;
#pragma unroll
            for (int j = 0; j < 8; j++)
                mx = fmaxf(mx, fmaxf(s[j][2 * r], s[j][2 * r + 1]));
            mx = fmaxf(mx, __shfl_xor_sync(0xffffffffu, mx, 1));
            mx = fmaxf(mx, __shfl_xor_sync(0xffffffffu, mx, 2));
            float mnew = fmaxf(mrow[r], mx);
            float corr = __expf(mrow[r] - mnew);
            float sum = 0.0f;
#pragma unroll
            for (int j = 0; j < 8; j++) {
                s[j][2 * r]     = __expf(s[j][2 * r]     - mnew);
                s[j][2 * r + 1] = __expf(s[j][2 * r + 1] - mnew);
                sum += s[j][2 * r] + s[j][2 * r + 1];
            }
            sum += __shfl_xor_sync(0xffffffffu, sum, 1);
            sum += __shfl_xor_sync(0xffffffffu, sum, 2);
            lrow[r] = lrow[r] * corr + sum;
            mrow[r] = mnew;
#pragma unroll
            for (int j = 0; j < 8; j++) {
                o[j][2 * r]     *= corr;
                o[j][2 * r + 1] *= corr;
            }
        }

        const uint32_t vaddr = st + 2 * AMAT
            + (uint32_t)((lane & 15) * 144 + (lane >> 4) * 16);
#pragma unroll
        for (int ks2 = 0; ks2 < 4; ks2++) {
            uint32_t pah[4], pal[4];
            float* s0 = s[2 * ks2];
            float* s1 = s[2 * ks2 + 1];
            split2(s0[0], s0[1], pah[0], pal[0]);
            split2(s0[2], s0[3], pah[1], pal[1]);
            split2(s1[0], s1[1], pah[2], pal[2]);
            split2(s1[2], s1[3], pah[3], pal[3]);

            uint32_t vrow = vaddr + (uint32_t)(ks2 * 16 * 144);
#pragma unroll
            for (int jd2 = 0; jd2 < 4; jd2++) {
                uint32_t vh[4], vl[4];
                uint32_t off = vrow + (uint32_t)(jd2 * 32);
                LDSM4T(vh[0], vh[1], vh[2], vh[3], off);
                LDSM4T(vl[0], vl[1], vl[2], vl[3], off + AMAT);
                MMA16816(o[2 * jd2],     pah, &vh[0]);
                MMA16816(o[2 * jd2],     pah, &vl[0]);
                MMA16816(o[2 * jd2],     pal, &vh[0]);
                MMA16816(o[2 * jd2 + 1], pah, &vh[2]);
                MMA16816(o[2 * jd2 + 1], pah, &vl[2]);
                MMA16816(o[2 * jd2 + 1], pal, &vh[2]);
            }
        }
        __syncthreads();
    }

    const int b = bh >> 4, h = bh & 15;
    const int G = lane >> 2, T = lane & 3;
#pragma unroll
    for (int r = 0; r < 2; r++) {
        float inv = 1.0f / lrow[r];
        int row = q0 + wq * 16 + G + r * 8;
        size_t base = ((size_t)b * Nn + row) * Cc + h * 64;
#pragma unroll
        for (int jd = 0; jd < 8; jd++) {
            float v0 = o[jd][2 * r] * inv;
            float v1 = o[jd][2 * r + 1] * inv;
            int col = jd * 8 + 2 * T;
            uint32_t hp, lp;
            split2(v0, v1, hp, lp);
            *(uint32_t*)&g_aoh[base + col] = hp;
            *(uint32_t*)&g_aol[base + col] = lp;
        }
    }
}

// ---------------------------------------------------------------------------
extern "C" void kernel_launch(void* const* d_in, const int* in_sizes, int n_in,
                              void* d_out, int out_size)
{
    const float* x     = (const float*)d_in[0];
    const float* w_in  = (const float*)d_in[1];
    const float* b_in  = (const float*)d_in[2];
    const float* w_out = (const float*)d_in[3];
    const float* b_out = (const float*)d_in[4];
    float* out = (float*)d_out;

    cudaFuncSetAttribute(gemm_mma<0>,
                         cudaFuncAttributeMaxDynamicSharedMemorySize, GSMEM);
    cudaFuncSetAttribute(gemm_mma<1>,
                         cudaFuncAttributeMaxDynamicSharedMemorySize, GSMEM);
    cudaFuncSetAttribute(attn_mma,
                         cudaFuncAttributeMaxDynamicSharedMemorySize, 2 * ASTG);

    cvt_kernel<<<(Bb * Nn * Cc / 4 + 255) / 256, 256>>>((const float4*)x, 0, Bb * Nn * Cc / 4);
    cvt_kernel<<<(3 * Cc * Cc / 4 + 255) / 256, 256>>>((const float4*)w_in, 1, 3 * Cc * Cc / 4);
    cvt_kernel<<<(Cc * Cc / 4 + 255) / 256, 256>>>((const float4*)w_out, 2, Cc * Cc / 4);

    // QKV projection: 8192 x 3072 x 1024 -> q/k/v bf16 hi/lo (q pre-scaled)
    gemm_mma<0><<<dim3(24, 64), 256, GSMEM>>>(b_in, nullptr);
    // Attention: 8 q-tiles x 128 (b,h)
    attn_mma<<<dim3(8, 128), 256, 2 * ASTG>>>();
    // Output projection: 8192 x 1024 x 1024
    gemm_mma<1><<<dim3(8, 64), 256, GSMEM>>>(b_out, out);
}